// round 7
// baseline (speedup 1.0000x reference)
#include <cuda_runtime.h>
#include <cstddef>

// x: (8, 16, 3, 256, 256) fp32; out: (128, 2, 256, 256) fp32
// out[bl, ch, hw] = plane(bl*3) - plane((bl-1)*3), zero when bl%16==0; ch0==ch1.
//
// R5 policy (streaming .cs stores to keep the input set L2-resident across
// graph replays) + Blackwell 256-bit vector ld/st (.v8.f32, sm_100+):
// each thread moves 32 B per access, halving LSU ops and L1tex wavefronts.

static constexpr int HW8 = 8192;          // 256*256/8 v8-chunks per plane
static constexpr int BL  = 128;           // 8*16
static constexpr int TOTAL8 = BL * HW8;   // 1,048,576 threads

__device__ __forceinline__ void ldg_v8(const float* p, float* r) {
    asm volatile(
        "ld.global.nc.v8.f32 {%0,%1,%2,%3,%4,%5,%6,%7}, [%8];"
        : "=f"(r[0]), "=f"(r[1]), "=f"(r[2]), "=f"(r[3]),
          "=f"(r[4]), "=f"(r[5]), "=f"(r[6]), "=f"(r[7])
        : "l"(p));
}

__device__ __forceinline__ void stg_cs_v8(float* p, const float* r) {
    asm volatile(
        "st.global.cs.v8.f32 [%0], {%1,%2,%3,%4,%5,%6,%7,%8};"
        :: "l"(p),
           "f"(r[0]), "f"(r[1]), "f"(r[2]), "f"(r[3]),
           "f"(r[4]), "f"(r[5]), "f"(r[6]), "f"(r[7])
        : "memory");
}

__global__ __launch_bounds__(256) void dummyflow_diff_kernel(
    const float* __restrict__ x, float* __restrict__ out)
{
    int idx = blockIdx.x * blockDim.x + threadIdx.x;
    if (idx >= TOTAL8) return;

    int bl = idx >> 13;          // idx / HW8
    int h8 = idx & (HW8 - 1);    // v8-chunk within plane
    int l  = bl & 15;

    // element offsets (floats); plane = 65536 floats
    size_t off = (size_t)h8 * 8;

    float v[8];
    if (l == 0) {
        #pragma unroll
        for (int i = 0; i < 8; i++) v[i] = 0.f;
    } else {
        const float* cur  = x + (size_t)(bl * 3)       * 65536 + off;
        const float* prev = x + (size_t)((bl - 1) * 3) * 65536 + off;
        float a[8], p[8];
        ldg_v8(cur, a);
        ldg_v8(prev, p);
        #pragma unroll
        for (int i = 0; i < 8; i++) v[i] = a[i] - p[i];
    }

    float* o = out + (size_t)(bl * 2) * 65536 + off;
    stg_cs_v8(o, v);            // channel 0
    stg_cs_v8(o + 65536, v);    // channel 1
}

extern "C" void kernel_launch(void* const* d_in, const int* in_sizes, int n_in,
                              void* d_out, int out_size)
{
    const float* x = (const float*)d_in[0];
    float* out = (float*)d_out;

    int threads = 256;
    int blocks = TOTAL8 / threads;   // 4096
    dummyflow_diff_kernel<<<blocks, threads>>>(x, out);
}